// round 2
// baseline (speedup 1.0000x reference)
#include <cuda_runtime.h>
#include <cstdint>

#define K1      100
#define H       256
#define ROWS    64
#define RPAD    68      // act buffer k-stride in floats
#define KBS     16      // k-chunk
#define THREADS 512

// smem (floats): actA[H*RPAD], actB[H*RPAD], wslab[2][KBS*256] (permuted),
//                hslab[2][KBS*128] (row-duplicated), w4s[256]
#define ACT_F   (H * RPAD)
#define WSLAB_F (KBS * 256)
#define HSLAB_F (KBS * 128)
#define SMEM_FLOATS (2*ACT_F + 2*WSLAB_F + 2*HSLAB_F + 256)
#define SMEM_BYTES  (SMEM_FLOATS * 4)

typedef unsigned long long ull;

__device__ __forceinline__ ull pack2(float lo, float hi) {
    ull r; asm("mov.b64 %0, {%1,%2};" : "=l"(r) : "f"(lo), "f"(hi)); return r;
}
__device__ __forceinline__ void unpack2(ull v, float& lo, float& hi) {
    asm("mov.b64 {%0,%1}, %2;" : "=f"(lo), "=f"(hi) : "l"(v));
}
// d += a*b on packed f32x2 (Blackwell FFMA2)
__device__ __forceinline__ void fma2(ull& d, ull a, ull b) {
    asm("fma.rn.f32x2 %0, %1, %2, %0;" : "+l"(d) : "l"(a), "l"(b));
}
__device__ __forceinline__ float tanh_fast(float x) {
    float y; asm("tanh.approx.f32 %0, %1;" : "=f"(y) : "f"(x)); return y;
}

// Per-chunk staging registers (loads issued early, stores after compute)
struct Stage {
    float2 w[4];
    float2 h;
};

// Load chunk [kb, kb+kc) of W (global) and h (act smem) into registers.
__device__ __forceinline__ Stage stage_load(const float* __restrict__ Wg, int kb, int kc,
                                            const float* act_in) {
    Stage s;
    int tid = threadIdx.x;
    int npair = kc * 128;                 // W float2 entries this chunk
#pragma unroll
    for (int t = 0; t < 4; t++) {
        int p = tid + t * THREADS;
        if (p < npair) {
            int k = p >> 7, pr = p & 127;
            s.w[t] = *(const float2*)(Wg + (size_t)(kb + k) * H + 2 * pr);
        }
    }
    if (tid < kc * 32) {                  // h row-pair entries
        int k = tid >> 5, rp = tid & 31;
        s.h = *(const float2*)(act_in + (size_t)(kb + k) * RPAD + 2 * rp);
    }
    return s;
}

// Scatter staged registers into the (permuted) w slab and duplicated h slab.
__device__ __forceinline__ void stage_store(const Stage& s, int kc,
                                            float* wsl, float* hsl) {
    int tid = threadIdx.x;
    int npair = kc * 128;
#pragma unroll
    for (int t = 0; t < 4; t++) {
        int p = tid + t * THREADS;
        if (p < npair) {
            int k = p >> 7, pr = p & 127;
            int sb   = pr >> 5;
            int cg   = (pr & 31) >> 2;
            int half = (pr >> 1) & 1;
            int i    = (pr & 1) * 2;
            int off  = k * 256 + sb * 64 + half * 32 + cg * 4 + i;
            *(float2*)(wsl + off) = s.w[t];
        }
    }
    if (tid < kc * 32) {
        int k = tid >> 5, rp = tid & 31;
        *(float4*)(hsl + k * 128 + rp * 4) = make_float4(s.h.x, s.h.x, s.h.y, s.h.y);
    }
}

// Compute one k-chunk: acc[r][cp] += dup(h[k][row_r]) * (w[k][j],w[k][j+1])
template<int KC>
__device__ __forceinline__ void comp_chunk(ull acc[16], const char* hp, const char* wp) {
#pragma unroll
    for (int k = 0; k < KC; k++) {
        ulonglong2 h01 = *(const ulonglong2*)(hp + k * 512);        // dup(r0), dup(r0+1)
        ulonglong2 h23 = *(const ulonglong2*)(hp + k * 512 + 16);   // dup(r0+2), dup(r0+3)
        ulonglong2 wA  = *(const ulonglong2*)(wp + k * 1024);       // (c0,c0+1),(c0+2,c0+3)
        ulonglong2 wB  = *(const ulonglong2*)(wp + k * 1024 + 128); // (c0+4..c0+7)
        fma2(acc[0],  h01.x, wA.x); fma2(acc[1],  h01.x, wA.y);
        fma2(acc[2],  h01.x, wB.x); fma2(acc[3],  h01.x, wB.y);
        fma2(acc[4],  h01.y, wA.x); fma2(acc[5],  h01.y, wA.y);
        fma2(acc[6],  h01.y, wB.x); fma2(acc[7],  h01.y, wB.y);
        fma2(acc[8],  h23.x, wA.x); fma2(acc[9],  h23.x, wA.y);
        fma2(acc[10], h23.x, wB.x); fma2(acc[11], h23.x, wB.y);
        fma2(acc[12], h23.y, wA.x); fma2(acc[13], h23.y, wA.y);
        fma2(acc[14], h23.y, wB.x); fma2(acc[15], h23.y, wB.y);
    }
}

// One MLP layer: act_out[j][r] = tanh( sum_k act_in[k][r] * W[k][j] + b[j] )
__device__ __forceinline__ void mlp_layer(
    const float* __restrict__ Wg, const float* __restrict__ bg,
    const float* act_in, float* act_out,
    float* wsl0, float* wsl1, float* hsl0, float* hsl1, int Kdim)
{
    int tid  = threadIdx.x;
    int lane = tid & 31, warp = tid >> 5;
    int colg = lane & 7, rowsub = lane >> 3;
    int wsb  = warp & 3, wrs = warp >> 2;
    int r0   = wrs * 16 + rowsub * 4;     // 4 rows r0..r0+3
    int c0   = wsb * 64 + colg * 8;       // 8 cols c0..c0+7

    ull acc[16];
#pragma unroll
    for (int cp = 0; cp < 4; cp++) {
        float2 b2 = *(const float2*)(bg + c0 + 2 * cp);
        ull bp = pack2(b2.x, b2.y);
        acc[cp] = bp; acc[4 + cp] = bp; acc[8 + cp] = bp; acc[12 + cp] = bp;
    }

    int nch = (Kdim + KBS - 1) / KBS;
    float* wbuf[2] = { wsl0, wsl1 };
    float* hbuf[2] = { hsl0, hsl1 };

    __syncthreads();   // act_in ready; all prior slab readers done
    {
        int kc0 = (Kdim < KBS) ? Kdim : KBS;
        Stage s0 = stage_load(Wg, 0, kc0, act_in);
        stage_store(s0, kc0, wbuf[0], hbuf[0]);
    }

    for (int c = 0; c < nch; c++) {
        __syncthreads();                  // slab c visible; slab c+1 buffer free
        int kb_n = (c + 1) * KBS;
        bool more = (c + 1 < nch);
        int kc_n = 0;
        Stage sn;
        if (more) {
            kc_n = Kdim - kb_n; if (kc_n > KBS) kc_n = KBS;
            sn = stage_load(Wg, kb_n, kc_n, act_in);   // LDGs issue here, land during compute
        }
        const char* hp = (const char*)hbuf[c & 1] + r0 * 8;
        const char* wp = (const char*)wbuf[c & 1] + wsb * 256 + colg * 16;
        int kc = Kdim - c * KBS; if (kc > KBS) kc = KBS;
        if (kc == KBS) comp_chunk<KBS>(acc, hp, wp);
        else           comp_chunk<4>(acc, hp, wp);     // only K1=100 tail (kc=4)
        if (more) stage_store(sn, kc_n, wbuf[(c + 1) & 1], hbuf[(c + 1) & 1]);
    }

    // Epilogue: tanh + transposed store [j][r] (non-duplicated)
    float v[4][8];
#pragma unroll
    for (int r = 0; r < 4; r++)
#pragma unroll
        for (int cp = 0; cp < 4; cp++) {
            float a, b;
            unpack2(acc[r * 4 + cp], a, b);
            v[r][2 * cp]     = tanh_fast(a);
            v[r][2 * cp + 1] = tanh_fast(b);
        }
#pragma unroll
    for (int j = 0; j < 8; j++) {
        *(float4*)(act_out + (size_t)(c0 + j) * RPAD + r0) =
            make_float4(v[0][j], v[1][j], v[2][j], v[3][j]);
    }
}

__global__ void __launch_bounds__(THREADS, 1)
gnn_mlp_kernel(const float* __restrict__ ea,
               const float* __restrict__ W1, const float* __restrict__ b1,
               const float* __restrict__ W2, const float* __restrict__ b2,
               const float* __restrict__ W3, const float* __restrict__ b3,
               const float* __restrict__ W4, const float* __restrict__ b4,
               float* __restrict__ out, int ntot)
{
    extern __shared__ float smem[];
    float* actA = smem;
    float* actB = actA + ACT_F;
    float* wsl0 = actB + ACT_F;
    float* wsl1 = wsl0 + WSLAB_F;
    float* hsl0 = wsl1 + WSLAB_F;
    float* hsl1 = hsl0 + HSLAB_F;
    float* w4s  = hsl1 + HSLAB_F;

    int row0 = blockIdx.x * ROWS;
    int tid  = threadIdx.x;

    // e-tile (ROWS x K1) -> actB transposed [k][r]; W4 -> smem
    for (int idx = tid; idx < ROWS * K1; idx += THREADS) {
        int r = idx / K1;
        int k = idx - r * K1;
        int row = row0 + r;
        actB[k * RPAD + r] = (row < ntot) ? ea[(size_t)row * K1 + k] : 0.0f;
    }
    if (tid < H) w4s[tid] = W4[tid];

    mlp_layer(W1, b1, actB, actA, wsl0, wsl1, hsl0, hsl1, K1);  // e   -> actA
    mlp_layer(W2, b2, actA, actB, wsl0, wsl1, hsl0, hsl1, H);   // actA-> actB
    mlp_layer(W3, b3, actB, actA, wsl0, wsl1, hsl0, hsl1, H);   // actB-> actA

    __syncthreads();   // layer-3 epilogue stores visible

    // Layer 4: out[r] = sigmoid( sum_k actA[k][r]*W4[k] + b4 )
    if (tid < ROWS) {
        int r = tid;
        float a0 = 0.f, a1 = 0.f, a2 = 0.f, a3 = 0.f;
#pragma unroll 8
        for (int k = 0; k < H; k += 4) {
            a0 += actA[(k + 0) * RPAD + r] * w4s[k + 0];
            a1 += actA[(k + 1) * RPAD + r] * w4s[k + 1];
            a2 += actA[(k + 2) * RPAD + r] * w4s[k + 2];
            a3 += actA[(k + 3) * RPAD + r] * w4s[k + 3];
        }
        float z = (a0 + a1) + (a2 + a3) + b4[0];
        int row = row0 + r;
        if (row < ntot) out[row] = 1.0f / (1.0f + expf(-z));
    }
}

extern "C" void kernel_launch(void* const* d_in, const int* in_sizes, int n_in,
                              void* d_out, int out_size)
{
    // Inputs: x, edge_index, edge_attr, W1, b1, W2, b2, W3, b3, W4, b4
    const float* ea = (const float*)d_in[2];
    const float* W1 = (const float*)d_in[3];
    const float* b1 = (const float*)d_in[4];
    const float* W2 = (const float*)d_in[5];
    const float* b2 = (const float*)d_in[6];
    const float* W3 = (const float*)d_in[7];
    const float* b3 = (const float*)d_in[8];
    const float* W4 = (const float*)d_in[9];
    const float* b4 = (const float*)d_in[10];
    float* out = (float*)d_out;

    int ntot = out_size;                  // 500000
    int grid = (ntot + ROWS - 1) / ROWS;  // 7813

    cudaFuncSetAttribute(gnn_mlp_kernel,
                         cudaFuncAttributeMaxDynamicSharedMemorySize, SMEM_BYTES);
    gnn_mlp_kernel<<<grid, THREADS, SMEM_BYTES>>>(ea, W1, b1, W2, b2, W3, b3,
                                                  W4, b4, out, ntot);
}

// round 4
// speedup vs baseline: 1.5701x; 1.5701x over previous
#include <cuda_runtime.h>
#include <cstdint>

#define K1      100
#define H       256
#define ROWS    80      // rows per block (500000 = 6250 * 80)
#define RPAD    84      // act k-row stride in floats (16B aligned)
#define KBS     16      // k-chunk
#define THREADS 320     // 10 warps; warp = 8 rows x 256 cols

#define ACT_F   (H * RPAD)
#define WSLAB_F (KBS * H)
#define SMEM_FLOATS (2*ACT_F + 2*WSLAB_F + H)
#define SMEM_BYTES  (SMEM_FLOATS * 4)

typedef unsigned long long ull;

__device__ __forceinline__ ull pack2(float lo, float hi) {
    ull r; asm("mov.b64 %0, {%1,%2};" : "=l"(r) : "f"(lo), "f"(hi)); return r;
}
__device__ __forceinline__ void unpack2(ull v, float& lo, float& hi) {
    asm("mov.b64 {%0,%1}, %2;" : "=f"(lo), "=f"(hi) : "l"(v));
}
__device__ __forceinline__ void fma2(ull& d, ull a, ull b) {
    asm("fma.rn.f32x2 %0, %1, %2, %0;" : "+l"(d) : "l"(a), "l"(b));
}

// ---- W chunk staging: rows [kb, kb+kc) of W (row-major K x 256), natural layout ----
__device__ __forceinline__ void stage_ld(float4 st[4], const float* __restrict__ Wg,
                                         int kb, int kc) {
    const float4* src = (const float4*)(Wg + (size_t)kb * H);
    int n = kc * (H / 4);
#pragma unroll
    for (int i = 0; i < 4; i++) {
        int idx = threadIdx.x + i * THREADS;
        if (idx < n) st[i] = src[idx];
    }
}
__device__ __forceinline__ void stage_st(const float4 st[4], float* buf, int kc) {
    float4* dst = (float4*)buf;
    int n = kc * (H / 4);
#pragma unroll
    for (int i = 0; i < 4; i++) {
        int idx = threadIdx.x + i * THREADS;
        if (idx < n) dst[idx] = st[i];
    }
}

// ---- inner compute over one k-chunk ----
// Lane owns cols {4*lane..+3} (accA) and {128+4*lane..+3} (accB); warp owns 8 rows.
// Both weight LDS.128 cover 512 contiguous bytes -> conflict-free (4 wf each).
// h loads are warp-uniform -> broadcast (1 wf each).
template<int KC>
__device__ __forceinline__ void comp_chunk(ull accA[16], ull accB[16],
                                           const float* hb, const float* wp) {
#pragma unroll
    for (int k = 0; k < KC; k++) {
        float4 h0 = *(const float4*)(hb + (size_t)k * RPAD);
        float4 h1 = *(const float4*)(hb + (size_t)k * RPAD + 4);
        ulonglong2 wA = *(const ulonglong2*)(wp + (size_t)k * H);        // cols 4L..4L+3
        ulonglong2 wB = *(const ulonglong2*)(wp + (size_t)k * H + 128);  // cols 128+4L..+3
        ull hd[8];
        hd[0] = pack2(h0.x, h0.x); hd[1] = pack2(h0.y, h0.y);
        hd[2] = pack2(h0.z, h0.z); hd[3] = pack2(h0.w, h0.w);
        hd[4] = pack2(h1.x, h1.x); hd[5] = pack2(h1.y, h1.y);
        hd[6] = pack2(h1.z, h1.z); hd[7] = pack2(h1.w, h1.w);
#pragma unroll
        for (int r = 0; r < 8; r++) {
            fma2(accA[r * 2],     hd[r], wA.x);
            fma2(accA[r * 2 + 1], hd[r], wA.y);
            fma2(accB[r * 2],     hd[r], wB.x);
            fma2(accB[r * 2 + 1], hd[r], wB.y);
        }
    }
}

// One layer: act_out[j][r] = tanh( sum_k act_in[k][r] * W[k][j] + b[j] )
__device__ __forceinline__ void mlp_layer(
    const float* __restrict__ Wg, const float* __restrict__ bg,
    const float* act_in, float* act_out, float* wsl0, float* wsl1, int Kdim)
{
    int lane = threadIdx.x & 31, warp = threadIdx.x >> 5;
    int r0  = warp * 8;       // warp's 8 rows
    int ca  = lane * 4;       // cols ca..ca+3
    int cb  = 128 + lane * 4; // cols cb..cb+3

    ull accA[16], accB[16];
#pragma unroll
    for (int cp = 0; cp < 2; cp++) {
        float2 bA = *(const float2*)(bg + ca + 2 * cp);
        float2 bB = *(const float2*)(bg + cb + 2 * cp);
        ull bpA = pack2(bA.x, bA.y), bpB = pack2(bB.x, bB.y);
#pragma unroll
        for (int r = 0; r < 8; r++) { accA[r * 2 + cp] = bpA; accB[r * 2 + cp] = bpB; }
    }

    int nch = (Kdim + KBS - 1) / KBS;
    float4 st[4];
    {
        int kc0 = (Kdim < KBS) ? Kdim : KBS;
        stage_ld(st, Wg, 0, kc0);
    }
    __syncthreads();   // act_in visible; prior readers of wsl buffers done

    for (int c = 0; c < nch; c++) {
        float* buf = (c & 1) ? wsl1 : wsl0;
        int kc = Kdim - c * KBS; if (kc > KBS) kc = KBS;
        stage_st(st, buf, kc);
        __syncthreads();                          // slab c visible (also fences buf reuse)
        if (c + 1 < nch) {
            int kcn = Kdim - (c + 1) * KBS; if (kcn > KBS) kcn = KBS;
            stage_ld(st, Wg, (c + 1) * KBS, kcn); // LDGs land during compute
        }
        const float* hb = act_in + (size_t)c * KBS * RPAD + r0;
        const float* wp = buf + ca;
        if (kc == KBS) comp_chunk<KBS>(accA, accB, hb, wp);
        else           comp_chunk<4>(accA, accB, hb, wp);  // K1 tail: 100-96=4 exactly
    }

    // tanh (accurate) + transposed store [j][r]
#pragma unroll
    for (int cp = 0; cp < 2; cp++) {
#pragma unroll
        for (int jj = 0; jj < 2; jj++) {
            int j  = 2 * cp + jj;
            float vA[8], vB[8];
#pragma unroll
            for (int r = 0; r < 8; r++) {
                float a0, a1, b0, b1;
                unpack2(accA[r * 2 + cp], a0, a1);
                unpack2(accB[r * 2 + cp], b0, b1);
                vA[r] = tanhf(jj ? a1 : a0);
                vB[r] = tanhf(jj ? b1 : b0);
            }
            float* dA = act_out + (size_t)(ca + j) * RPAD + r0;
            float* dB = act_out + (size_t)(cb + j) * RPAD + r0;
            *(float4*)dA       = make_float4(vA[0], vA[1], vA[2], vA[3]);
            *(float4*)(dA + 4) = make_float4(vA[4], vA[5], vA[6], vA[7]);
            *(float4*)dB       = make_float4(vB[0], vB[1], vB[2], vB[3]);
            *(float4*)(dB + 4) = make_float4(vB[4], vB[5], vB[6], vB[7]);
        }
    }
}

__global__ void __launch_bounds__(THREADS, 1)
gnn_mlp_kernel(const float* __restrict__ ea,
               const float* __restrict__ W1, const float* __restrict__ b1,
               const float* __restrict__ W2, const float* __restrict__ b2,
               const float* __restrict__ W3, const float* __restrict__ b3,
               const float* __restrict__ W4, const float* __restrict__ b4,
               float* __restrict__ out, int ntot)
{
    extern __shared__ float smem[];
    float* actA = smem;
    float* actB = actA + ACT_F;
    float* wsl0 = actB + ACT_F;
    float* wsl1 = wsl0 + WSLAB_F;
    float* w4s  = wsl1 + WSLAB_F;

    int row0 = blockIdx.x * ROWS;
    int tid  = threadIdx.x;

    // e-tile (ROWS x K1) -> actB transposed [k][r]
    for (int idx = tid; idx < ROWS * K1; idx += THREADS) {
        int r = idx / K1;
        int k = idx - r * K1;
        int row = row0 + r;
        actB[k * RPAD + r] = (row < ntot) ? ea[(size_t)row * K1 + k] : 0.0f;
    }
    if (tid < H) w4s[tid] = W4[tid];

    mlp_layer(W1, b1, actB, actA, wsl0, wsl1, K1);  // e    -> actA
    mlp_layer(W2, b2, actA, actB, wsl0, wsl1, H);   // actA -> actB
    mlp_layer(W3, b3, actB, actA, wsl0, wsl1, H);   // actB -> actA

    __syncthreads();   // layer-3 epilogue stores visible

    // Layer 4: out[r] = sigmoid( sum_k actA[k][r]*W4[k] + b4 )
    if (tid < ROWS) {
        int r = tid;
        float a0 = 0.f, a1 = 0.f, a2 = 0.f, a3 = 0.f;
#pragma unroll 8
        for (int k = 0; k < H; k += 4) {
            a0 += actA[(k + 0) * RPAD + r] * w4s[k + 0];
            a1 += actA[(k + 1) * RPAD + r] * w4s[k + 1];
            a2 += actA[(k + 2) * RPAD + r] * w4s[k + 2];
            a3 += actA[(k + 3) * RPAD + r] * w4s[k + 3];
        }
        float z = (a0 + a1) + (a2 + a3) + b4[0];
        int row = row0 + r;
        if (row < ntot) out[row] = 1.0f / (1.0f + expf(-z));
    }
}

extern "C" void kernel_launch(void* const* d_in, const int* in_sizes, int n_in,
                              void* d_out, int out_size)
{
    // Inputs: x, edge_index, edge_attr, W1, b1, W2, b2, W3, b3, W4, b4
    const float* ea = (const float*)d_in[2];
    const float* W1 = (const float*)d_in[3];
    const float* b1 = (const float*)d_in[4];
    const float* W2 = (const float*)d_in[5];
    const float* b2 = (const float*)d_in[6];
    const float* W3 = (const float*)d_in[7];
    const float* b3 = (const float*)d_in[8];
    const float* W4 = (const float*)d_in[9];
    const float* b4 = (const float*)d_in[10];
    float* out = (float*)d_out;

    int ntot = out_size;                  // 500000
    int grid = (ntot + ROWS - 1) / ROWS;  // 6250

    cudaFuncSetAttribute(gnn_mlp_kernel,
                         cudaFuncAttributeMaxDynamicSharedMemorySize, SMEM_BYTES);
    gnn_mlp_kernel<<<grid, THREADS, SMEM_BYTES>>>(ea, W1, b1, W2, b2, W3, b3,
                                                  W4, b4, out, ntot);
}